// round 15
// baseline (speedup 1.0000x reference)
#include <cuda_runtime.h>
#include <cuda_bf16.h>
#include <cstdint>

#define BB 8
#define TT 2048
#define DD 1024
#define NTOK (BB*TT)       // 16384
#define ROWF4 (DD/4)       // 256

// ---------------- scratch (no allocations allowed) ----------------
// float units of SZ=NTOK*DD: hb bf16 [0,.5) | xb bf16 [.5,1) | qkv bf16 [1,2.5) |
// tanha bf16 [2.5,3) | b fp32 [3,4) | dn fp32 [4,5)
__device__ float g_scratch[(size_t)5 * NTOK * DD];
// weights: qkv bf16 T [0,3W) | Wa bf16 T at 3W | Wb tf32 T at 4W | Wp tf32 T at 5W
__device__ float g_wt[(size_t)6 * DD * DD];
__device__ float g_bias[5120];                 // bqkv(3072) | ba(1024) | bb(1024)

// ---------------- helpers ----------------
__device__ __forceinline__ float sigmoidf_(float x) {
    return 1.0f / (1.0f + __expf(-x));
}
__device__ __forceinline__ float to_tf32(float x) {
    float r;
    asm("cvt.rna.tf32.f32 %0, %1;" : "=f"(r) : "f"(x));
    return r;
}
__device__ __forceinline__ uint32_t s2u(const void* p) {
    return (uint32_t)__cvta_generic_to_shared(p);
}
__device__ __forceinline__ float4 bf4(uint2 u) {
    __nv_bfloat162 lo = *(__nv_bfloat162*)&u.x;
    __nv_bfloat162 hi = *(__nv_bfloat162*)&u.y;
    float2 a = __bfloat1622float2(lo);
    float2 b = __bfloat1622float2(hi);
    return make_float4(a.x, a.y, b.x, b.y);
}

#define MMA_TF32(c, a, b)                                                       \
    asm volatile(                                                               \
        "mma.sync.aligned.m16n8k8.row.col.f32.tf32.tf32.f32 "                   \
        "{%0,%1,%2,%3},{%4,%5,%6,%7},{%8,%9},{%0,%1,%2,%3};\n"                  \
        : "+f"((c)[0]), "+f"((c)[1]), "+f"((c)[2]), "+f"((c)[3])                \
        : "r"((a)[0]), "r"((a)[1]), "r"((a)[2]), "r"((a)[3]),                   \
          "r"((b)[0]), "r"((b)[1]))

#define MMA_BF16(c, a, b)                                                       \
    asm volatile(                                                               \
        "mma.sync.aligned.m16n8k16.row.col.f32.bf16.bf16.f32 "                  \
        "{%0,%1,%2,%3},{%4,%5,%6,%7},{%8,%9},{%0,%1,%2,%3};\n"                  \
        : "+f"((c)[0]), "+f"((c)[1]), "+f"((c)[2]), "+f"((c)[3])                \
        : "r"((a)[0]), "r"((a)[1]), "r"((a)[2]), "r"((a)[3]),                   \
          "r"((b)[0]), "r"((b)[1]))

#define LDSM4(r0, r1, r2, r3, addr)                                             \
    asm volatile("ldmatrix.sync.aligned.m8n8.x4.shared.b16 {%0,%1,%2,%3}, [%4];"\
        : "=r"(r0), "=r"(r1), "=r"(r2), "=r"(r3) : "r"(addr))

#define CP16(smem_addr, gptr)                                                   \
    asm volatile("cp.async.cg.shared.global [%0], [%1], 16;"                    \
                 :: "r"(smem_addr), "l"(gptr) : "memory")
#define CP_COMMIT() asm volatile("cp.async.commit_group;" ::: "memory")

// ---------------- prep: transpose weights (qkv,Wa->bf16; Wb,Wp->tf32); bias concat ----------------
__global__ void prep_kernel(const float* __restrict__ Wq, const float* __restrict__ Wk,
                            const float* __restrict__ Wv, const float* __restrict__ Wa,
                            const float* __restrict__ Wb, const float* __restrict__ Wp,
                            const float* __restrict__ bq, const float* __restrict__ bk,
                            const float* __restrict__ bv, const float* __restrict__ ba,
                            const float* __restrict__ bb) {
    const int s = blockIdx.z;
    if (s == 6) {
        if (blockIdx.x != 0 || blockIdx.y != 0) return;
        const int tid = threadIdx.y * 32 + threadIdx.x;
        for (int i = tid; i < 1024; i += 256) {
            g_bias[i]        = bq[i];
            g_bias[1024 + i] = bk[i];
            g_bias[2048 + i] = bv[i];
            g_bias[3072 + i] = ba[i];
            g_bias[4096 + i] = bb[i];
        }
        return;
    }
    const float* srcs[6] = {Wq, Wk, Wv, Wa, Wb, Wp};
    const float* S = srcs[s];
    __shared__ float t[32][33];
    const int bx = blockIdx.x * 32, by = blockIdx.y * 32;
    const int tx = threadIdx.x, ty = threadIdx.y;
#pragma unroll
    for (int i = 0; i < 4; i++)
        t[ty + 8 * i][tx] = S[(size_t)(by + ty + 8 * i) * DD + bx + tx];
    __syncthreads();
    if (s < 3) {
        __nv_bfloat16* D16 = (__nv_bfloat16*)g_wt + (size_t)s * DD * DD;
#pragma unroll
        for (int i = 0; i < 4; i++)
            D16[(size_t)(bx + ty + 8 * i) * DD + by + tx] =
                __float2bfloat16(t[tx][ty + 8 * i]);
    } else if (s == 3) {
        __nv_bfloat16* D16 = (__nv_bfloat16*)(g_wt + (size_t)3 * DD * DD);
#pragma unroll
        for (int i = 0; i < 4; i++)
            D16[(size_t)(bx + ty + 8 * i) * DD + by + tx] =
                __float2bfloat16(t[tx][ty + 8 * i]);
    } else {
        float* D = g_wt + (size_t)s * DD * DD;
#pragma unroll
        for (int i = 0; i < 4; i++)
            D[(size_t)(bx + ty + 8 * i) * DD + by + tx] = to_tf32(t[tx][ty + 8 * i]);
    }
}

// ---------------- zc_rms: hb = bf16(zc_rms(x)); xb = bf16(x) ----------------
__global__ void zc_rms_kernel(const float4* __restrict__ x,
                              const float4* __restrict__ g,
                              uint2* __restrict__ out,
                              uint2* __restrict__ xb) {
    __shared__ float red[16];
    const int row = blockIdx.x;
    const int tid = threadIdx.x;
    const size_t base = (size_t)row * ROWF4 + tid;

    float4 v = x[base];
    float s  = v.x + v.y + v.z + v.w;
    float s2 = v.x*v.x + v.y*v.y + v.z*v.z + v.w*v.w;
#pragma unroll
    for (int o = 16; o; o >>= 1) {
        s  += __shfl_xor_sync(0xffffffffu, s,  o);
        s2 += __shfl_xor_sync(0xffffffffu, s2, o);
    }
    const int w = tid >> 5, l = tid & 31;
    if (l == 0) { red[w] = s; red[8 + w] = s2; }
    __syncthreads();
    s = 0.f; s2 = 0.f;
#pragma unroll
    for (int i = 0; i < 8; i++) { s += red[i]; s2 += red[8 + i]; }

    const float mean = s * (1.0f / DD);
    const float var  = s2 * (1.0f / DD) - mean * mean;
    const float r    = rsqrtf(var + 1e-8f);

    float4 gv = g[tid];
    __nv_bfloat162 lo = __floats2bfloat162_rn((v.x - mean) * r * gv.x,
                                              (v.y - mean) * r * gv.y);
    __nv_bfloat162 hi = __floats2bfloat162_rn((v.z - mean) * r * gv.z,
                                              (v.w - mean) * r * gv.w);
    uint2 o;
    o.x = *(uint32_t*)&lo;
    o.y = *(uint32_t*)&hi;
    out[base] = o;

    __nv_bfloat162 xlo = __floats2bfloat162_rn(v.x, v.y);
    __nv_bfloat162 xhi = __floats2bfloat162_rn(v.z, v.w);
    uint2 xo;
    xo.x = *(uint32_t*)&xlo;
    xo.y = *(uint32_t*)&xhi;
    xb[base] = xo;
}

// ---------------- fused conv3+sigmoid (q,k,v bf16) + l2norm + delta + zc_rms ----------------
// qkv bf16 [16384,3072]; ta bf16 [16384,1024] (already tanh'd); bfp fp32 [16384,1024]
#define TCHUNK 8
__global__ void conv_delta_kernel(const uint2* __restrict__ qkv,
                                  const uint2* __restrict__ ta,
                                  const float4* __restrict__ bfp,
                                  const float* __restrict__ wq, const float* __restrict__ cbq,
                                  const float* __restrict__ wk, const float* __restrict__ cbk,
                                  const float* __restrict__ wv, const float* __restrict__ cbv,
                                  const float4* __restrict__ g2,
                                  float4* __restrict__ out) {
    __shared__ float redA[2][16];
    __shared__ float redB[2][16];
    const int row0 = blockIdx.x * TCHUNK;
    const int tid = threadIdx.x;
    const int t0 = row0 & (TT - 1);
    const int d0 = tid * 4;
    const int w = tid >> 5, l = tid & 31;

    float cw[3][12], cbr[3][4];
#pragma unroll
    for (int j = 0; j < 4; j++) {
#pragma unroll
        for (int c = 0; c < 3; c++) {
            cw[0][j * 3 + c] = wq[(d0 + j) * 3 + c];
            cw[1][j * 3 + c] = wk[(d0 + j) * 3 + c];
            cw[2][j * 3 + c] = wv[(d0 + j) * 3 + c];
        }
        cbr[0][j] = cbq[d0 + j];
        cbr[1][j] = cbk[d0 + j];
        cbr[2][j] = cbv[d0 + j];
    }
    const float4 g2v = g2[tid];

    const size_t qbase = (size_t)row0 * 768 + tid;
    const float4 Z = make_float4(0.f, 0.f, 0.f, 0.f);

    float4 qm, qc, km, kc, vm, vc;
    qc = bf4(qkv[qbase]);
    kc = bf4(qkv[qbase + 256]);
    vc = bf4(qkv[qbase + 512]);
    if (t0 > 0) {
        qm = bf4(qkv[qbase - 768]);
        km = bf4(qkv[qbase - 768 + 256]);
        vm = bf4(qkv[qbase - 768 + 512]);
    } else { qm = Z; km = Z; vm = Z; }

    for (int i = 0; i < TCHUNK; i++) {
        const int row = row0 + i;
        const int t = t0 + i;
        const size_t qb = qbase + (size_t)i * 768;
        float4 qp, kp, vp;
        if (t < TT - 1) {
            qp = bf4(qkv[qb + 768]);
            kp = bf4(qkv[qb + 768 + 256]);
            vp = bf4(qkv[qb + 768 + 512]);
        } else { qp = Z; kp = Z; vp = Z; }

        const size_t rb = (size_t)row * 256 + tid;
        float4 av = bf4(ta[rb]);        // already tanh(a)
        float4 bv = bfp[rb];

        float4 qv, kv, vv;
#define C1(st, j, m, c, p) sigmoidf_(fmaf(cw[st][j*3+0], (m), fmaf(cw[st][j*3+1], (c), fmaf(cw[st][j*3+2], (p), cbr[st][j]))))
        qv.x = C1(0, 0, qm.x, qc.x, qp.x); qv.y = C1(0, 1, qm.y, qc.y, qp.y);
        qv.z = C1(0, 2, qm.z, qc.z, qp.z); qv.w = C1(0, 3, qm.w, qc.w, qp.w);
        kv.x = C1(1, 0, km.x, kc.x, kp.x); kv.y = C1(1, 1, km.y, kc.y, kp.y);
        kv.z = C1(1, 2, km.z, kc.z, kp.z); kv.w = C1(1, 3, km.w, kc.w, kp.w);
        vv.x = C1(2, 0, vm.x, vc.x, vp.x); vv.y = C1(2, 1, vm.y, vc.y, vp.y);
        vv.z = C1(2, 2, vm.z, vc.z, vp.z); vv.w = C1(2, 3, vm.w, vc.w, vp.w);
#undef C1
        qm = qc; qc = qp; km = kc; kc = kp; vm = vc; vc = vp;

        const int par = i & 1;
        float sq = qv.x*qv.x + qv.y*qv.y + qv.z*qv.z + qv.w*qv.w;
        float sk = kv.x*kv.x + kv.y*kv.y + kv.z*kv.z + kv.w*kv.w;
#pragma unroll
        for (int o = 16; o; o >>= 1) {
            sq += __shfl_xor_sync(0xffffffffu, sq, o);
            sk += __shfl_xor_sync(0xffffffffu, sk, o);
        }
        if (l == 0) { redA[par][w] = sq; redA[par][8 + w] = sk; }
        __syncthreads();
        sq = 0.f; sk = 0.f;
#pragma unroll
        for (int j = 0; j < 8; j++) { sq += redA[par][j]; sk += redA[par][8 + j]; }

        const float rq = rsqrtf(sq + 1e-8f);
        const float rk = rsqrtf(sk + 1e-8f);

        float dd0 = fmaf(av.x, (qv.x*rq)*(kv.x*rk)*vv.x, bv.x);
        float dd1 = fmaf(av.y, (qv.y*rq)*(kv.y*rk)*vv.y, bv.y);
        float dd2 = fmaf(av.z, (qv.z*rq)*(kv.z*rk)*vv.z, bv.z);
        float dd3 = fmaf(av.w, (qv.w*rq)*(kv.w*rk)*vv.w, bv.w);

        float s  = dd0 + dd1 + dd2 + dd3;
        float s2 = dd0*dd0 + dd1*dd1 + dd2*dd2 + dd3*dd3;
#pragma unroll
        for (int o = 16; o; o >>= 1) {
            s  += __shfl_xor_sync(0xffffffffu, s,  o);
            s2 += __shfl_xor_sync(0xffffffffu, s2, o);
        }
        if (l == 0) { redB[par][w] = s; redB[par][8 + w] = s2; }
        __syncthreads();
        s = 0.f; s2 = 0.f;
#pragma unroll
        for (int j = 0; j < 8; j++) { s += redB[par][j]; s2 += redB[par][8 + j]; }

        const float mean = s * (1.0f / DD);
        const float var  = s2 * (1.0f / DD) - mean * mean;
        const float r    = rsqrtf(var + 1e-8f);

        float4 o;
        o.x = to_tf32((dd0 - mean) * r * g2v.x);
        o.y = to_tf32((dd1 - mean) * r * g2v.y);
        o.z = to_tf32((dd2 - mean) * r * g2v.z);
        o.w = to_tf32((dd3 - mean) * r * g2v.w);
        out[(size_t)row * ROWF4 + tid] = o;
    }
}

// ======================= tf32 GEMM (R10 winner) =======================
#define TPITCH   144
#define AS_BYTES (128 * TPITCH)
#define BS_BYTES (128 * TPITCH)
#define STAGE_BYTES (AS_BYTES + BS_BYTES)        // 36864
#define NUM_STAGES 3
#define SMEM_GEMM (NUM_STAGES * STAGE_BYTES)     // 110592 (2 CTA/SM)

template <int EPI>   // 0: fp32 out; 1: residual epilogue
__global__ __launch_bounds__(128, 2)
void gemm_kernel(const float* __restrict__ A,
                 const float* __restrict__ Wt,
                 const float* __restrict__ bias,
                 const float* __restrict__ X,
                 float* __restrict__ C, const int ldc) {
    extern __shared__ __align__(16) char smem[];
    const int tid = threadIdx.x;
    const int m0 = blockIdx.y * 128;
    const int n0 = blockIdx.x * 128;
    const int warp = tid >> 5, lane = tid & 31;
    const int g = lane >> 2, tg = lane & 3;
    const int mBase = (warp >> 1) * 64;
    const int nBase = (warp & 1) * 64;

    const uint32_t smem_u = s2u(smem);

    const int rowL = tid >> 3, k4L = tid & 7;
    const float* gA = A  + (size_t)(m0 + rowL) * DD + k4L * 4;
    const float* gB = Wt + (size_t)(n0 + rowL) * DD + k4L * 4;

    const int q = lane >> 3, e = lane & 7;
    uint32_t aoff[4], boff[4];
#pragma unroll
    for (int mi = 0; mi < 4; mi++)
        aoff[mi] = (uint32_t)((mBase + mi * 16 + e + ((q & 1) << 3)) * TPITCH + ((q >> 1) << 4));
#pragma unroll
    for (int p = 0; p < 4; p++)
        boff[p] = (uint32_t)((nBase + p * 16 + ((q >> 1) << 3) + e) * TPITCH + ((q & 1) << 4));

    float acc[4][8][4];
#pragma unroll
    for (int mi = 0; mi < 4; mi++)
#pragma unroll
        for (int ni = 0; ni < 8; ni++)
#pragma unroll
            for (int i = 0; i < 4; i++) acc[mi][ni][i] = 0.f;

#define LOAD_CHUNK(k0, stage)                                                   \
    {                                                                           \
        const uint32_t sA0 = smem_u + (stage) * STAGE_BYTES;                    \
        const uint32_t sB0 = sA0 + AS_BYTES;                                    \
        _Pragma("unroll")                                                       \
        for (int i = 0; i < 8; i++)                                             \
            CP16(sA0 + (rowL + i * 16) * TPITCH + k4L * 16,                     \
                 gA + (size_t)(i * 16) * DD + (k0));                            \
        _Pragma("unroll")                                                       \
        for (int i = 0; i < 8; i++)                                             \
            CP16(sB0 + (rowL + i * 16) * TPITCH + k4L * 16,                     \
                 gB + (size_t)(i * 16) * DD + (k0));                            \
    }

#define FRAG_LOAD(b, kb)                                                        \
    {                                                                           \
        _Pragma("unroll")                                                       \
        for (int mi = 0; mi < 4; mi++)                                          \
            LDSM4(af[b][mi][0], af[b][mi][1], af[b][mi][2], af[b][mi][3],       \
                  sA + aoff[mi] + (kb));                                        \
        _Pragma("unroll")                                                       \
        for (int p = 0; p < 4; p++)                                             \
            LDSM4(bf[b][2 * p][0], bf[b][2 * p][1],                             \
                  bf[b][2 * p + 1][0], bf[b][2 * p + 1][1],                     \
                  sB + boff[p] + (kb));                                         \
    }

    LOAD_CHUNK(0, 0);  CP_COMMIT();
    LOAD_CHUNK(32, 1); CP_COMMIT();

    uint32_t af[2][4][4], bf[2][8][2];

    for (int kt = 0; kt < 32; ++kt) {
        if (kt < 31) asm volatile("cp.async.wait_group 1;" ::: "memory");
        else         asm volatile("cp.async.wait_group 0;" ::: "memory");
        __syncthreads();

        const int s = kt % 3;
        const uint32_t sA = smem_u + s * STAGE_BYTES;
        const uint32_t sB = sA + AS_BYTES;

        const bool doPf = (kt + 2 < 32);
        const int pfk0 = (kt + 2) * 32;
        const int pfs = (kt + 2) % 3;
        const uint32_t pA = smem_u + pfs * STAGE_BYTES;
        const uint32_t pB = pA + AS_BYTES;

        FRAG_LOAD(0, 0);

#pragma unroll
        for (int kk8 = 0; kk8 < 4; kk8++) {
            const int cur = kk8 & 1;
            if (doPf) {
#pragma unroll
                for (int j = 0; j < 2; j++) {
                    const int i = kk8 * 2 + j;
                    CP16(pA + (rowL + i * 16) * TPITCH + k4L * 16,
                         gA + (size_t)(i * 16) * DD + pfk0);
                    CP16(pB + (rowL + i * 16) * TPITCH + k4L * 16,
                         gB + (size_t)(i * 16) * DD + pfk0);
                }
            }
            if (kk8 < 3) {
                const int nxt = cur ^ 1;
                const uint32_t kbn = (kk8 + 1) * 32;
                FRAG_LOAD(nxt, kbn);
            }
#pragma unroll
            for (int mi = 0; mi < 4; mi++)
#pragma unroll
                for (int ni = 0; ni < 8; ni++)
                    MMA_TF32(acc[mi][ni], af[cur][mi], bf[cur][ni]);
        }
        if (doPf) CP_COMMIT();
    }
#undef LOAD_CHUNK
#undef FRAG_LOAD

#pragma unroll
    for (int mi = 0; mi < 4; mi++) {
#pragma unroll
        for (int ni = 0; ni < 8; ni++) {
            const int r = m0 + mBase + mi * 16 + g;
            const int c = n0 + nBase + ni * 8 + 2 * tg;
            const float b0 = __ldg(bias + c);
            const float b1 = __ldg(bias + c + 1);
#pragma unroll
            for (int half = 0; half < 2; half++) {
                const int rr = r + half * 8;
                float da = acc[mi][ni][half * 2 + 0] + b0;
                float db = acc[mi][ni][half * 2 + 1] + b1;
                if (EPI == 1) {
                    const float sa = da * sigmoidf_(da);   // silu
                    const float sb = db * sigmoidf_(db);
                    const float2 xv = *(const float2*)(X + (size_t)rr * DD + c);
                    *(float2*)(C + (size_t)rr * ldc + c) =
                        make_float2(xv.x + sigmoidf_(sa) * da,
                                    xv.y + sigmoidf_(sb) * db);
                } else {
                    *(float2*)(C + (size_t)rr * ldc + c) = make_float2(da, db);
                }
            }
        }
    }
}

// ======================= bf16 GEMM, m16n8k16 =======================
// EPI 0: bias + bf16 store (qkv); EPI 1: tanh(acc+bias) bf16 store (a-path)
template <int EPI>
__global__ __launch_bounds__(128, 2)
void gemm_bf16_kernel(const __nv_bfloat16* __restrict__ A,
                      const __nv_bfloat16* __restrict__ Wt,  // [n][k], pitch 1024
                      const float* __restrict__ bias,
                      __nv_bfloat16* __restrict__ C, const int ldc) {
    extern __shared__ __align__(16) char smem[];
    const int tid = threadIdx.x;
    const int m0 = blockIdx.y * 128;
    const int n0 = blockIdx.x * 128;
    const int warp = tid >> 5, lane = tid & 31;
    const int g = lane >> 2, tg = lane & 3;
    const int mBase = (warp >> 1) * 64;
    const int nBase = (warp & 1) * 64;

    const uint32_t smem_u = s2u(smem);

    const int rowL = tid >> 3, k4L = tid & 7;
    const __nv_bfloat16* gA = A  + (size_t)(m0 + rowL) * DD + k4L * 8;
    const __nv_bfloat16* gB = Wt + (size_t)(n0 + rowL) * DD + k4L * 8;

    const int q = lane >> 3, e = lane & 7;
    uint32_t aoff[4], boff[4];
#pragma unroll
    for (int mi = 0; mi < 4; mi++)
        aoff[mi] = (uint32_t)((mBase + mi * 16 + e + ((q & 1) << 3)) * TPITCH + ((q >> 1) << 4));
#pragma unroll
    for (int p = 0; p < 4; p++)
        boff[p] = (uint32_t)((nBase + p * 16 + ((q >> 1) << 3) + e) * TPITCH + ((q & 1) << 4));

    float acc[4][8][4];
#pragma unroll
    for (int mi = 0; mi < 4; mi++)
#pragma unroll
        for (int ni = 0; ni < 8; ni++)
#pragma unroll
            for (int i = 0; i < 4; i++) acc[mi][ni][i] = 0.f;

#define LOAD_CHUNK_B(k0, stage)                                                 \
    {                                                                           \
        const uint32_t sA0 = smem_u + (stage) * STAGE_BYTES;                    \
        const uint32_t sB0 = sA0 + AS_BYTES;                                    \
        _Pragma("unroll")                                                       \
        for (int i = 0; i < 8; i++)                                             \
            CP16(sA0 + (rowL + i * 16) * TPITCH + k4L * 16,                     \
                 gA + (size_t)(i * 16) * DD + (k0));                            \
        _Pragma("unroll")                                                       \
        for (int i = 0; i < 8; i++)                                             \
            CP16(sB0 + (rowL + i * 16) * TPITCH + k4L * 16,                     \
                 gB + (size_t)(i * 16) * DD + (k0));                            \
    }

#define FRAG_LOAD_B(b, kb)                                                      \
    {                                                                           \
        _Pragma("unroll")                                                       \
        for (int mi = 0; mi < 4; mi++)                                          \
            LDSM4(af[b][mi][0], af[b][mi][1], af[b][mi][2], af[b][mi][3],       \
                  sA + aoff[mi] + (kb));                                        \
        _Pragma("unroll")                                                       \
        for (int p = 0; p < 4; p++)                                             \
            LDSM4(bf[b][2 * p][0], bf[b][2 * p][1],                             \
                  bf[b][2 * p + 1][0], bf[b][2 * p + 1][1],                     \
                  sB + boff[p] + (kb));                                         \
    }

    LOAD_CHUNK_B(0, 0);  CP_COMMIT();
    LOAD_CHUNK_B(64, 1); CP_COMMIT();

    uint32_t af[2][4][4], bf[2][8][2];

    for (int kt = 0; kt < 16; ++kt) {
        if (kt < 15) asm volatile("cp.async.wait_group 1;" ::: "memory");
        else         asm volatile("cp.async.wait_group 0;" ::: "memory");
        __syncthreads();

        const int s = kt % 3;
        const uint32_t sA = smem_u + s * STAGE_BYTES;
        const uint32_t sB = sA + AS_BYTES;

        const bool doPf = (kt + 2 < 16);
        const int pfk0 = (kt + 2) * 64;
        const int pfs = (kt + 2) % 3;
        const uint32_t pA = smem_u + pfs * STAGE_BYTES;
        const uint32_t pB = pA + AS_BYTES;

        FRAG_LOAD_B(0, 0);

#pragma unroll
        for (int kk8 = 0; kk8 < 4; kk8++) {   // each step covers k=16
            const int cur = kk8 & 1;
            if (doPf) {
#pragma unroll
                for (int j = 0; j < 2; j++) {
                    const int i = kk8 * 2 + j;
                    CP16(pA + (rowL + i * 16) * TPITCH + k4L * 16,
                         gA + (size_t)(i * 16) * DD + pfk0);
                    CP16(pB + (rowL + i * 16) * TPITCH + k4L * 16,
                         gB + (size_t)(i * 16) * DD + pfk0);
                }
            }
            if (kk8 < 3) {
                const int nxt = cur ^ 1;
                const uint32_t kbn = (kk8 + 1) * 32;   // 16 bf16 = 32 bytes
                FRAG_LOAD_B(nxt, kbn);
            }
#pragma unroll
            for (int mi = 0; mi < 4; mi++)
#pragma unroll
                for (int ni = 0; ni < 8; ni++)
                    MMA_BF16(acc[mi][ni], af[cur][mi], bf[cur][ni]);
        }
        if (doPf) CP_COMMIT();
    }
#undef LOAD_CHUNK_B
#undef FRAG_LOAD_B

#pragma unroll
    for (int mi = 0; mi < 4; mi++) {
#pragma unroll
        for (int ni = 0; ni < 8; ni++) {
            const int r = m0 + mBase + mi * 16 + g;
            const int c = n0 + nBase + ni * 8 + 2 * tg;
            const float b0 = __ldg(bias + c);
            const float b1 = __ldg(bias + c + 1);
#pragma unroll
            for (int half = 0; half < 2; half++) {
                const int rr = r + half * 8;
                float da = acc[mi][ni][half * 2 + 0] + b0;
                float db = acc[mi][ni][half * 2 + 1] + b1;
                if (EPI == 1) { da = tanhf(da); db = tanhf(db); }
                __nv_bfloat162 pk = __floats2bfloat162_rn(da, db);
                *(__nv_bfloat162*)(C + (size_t)rr * ldc + c) = pk;
            }
        }
    }
}

// ---------------- launch ----------------
extern "C" void kernel_launch(void* const* d_in, const int* in_sizes, int n_in,
                              void* d_out, int out_size) {
    const float* x   = (const float*)d_in[0];
    const float* g1  = (const float*)d_in[1];
    const float* Wq  = (const float*)d_in[2];
    const float* bq  = (const float*)d_in[3];
    const float* Wk  = (const float*)d_in[4];
    const float* bk  = (const float*)d_in[5];
    const float* Wv  = (const float*)d_in[6];
    const float* bv  = (const float*)d_in[7];
    const float* wqc = (const float*)d_in[8];
    const float* bqc = (const float*)d_in[9];
    const float* wkc = (const float*)d_in[10];
    const float* bkc = (const float*)d_in[11];
    const float* wvc = (const float*)d_in[12];
    const float* bvc = (const float*)d_in[13];
    const float* Wa  = (const float*)d_in[14];
    const float* ba  = (const float*)d_in[15];
    const float* Wb  = (const float*)d_in[16];
    const float* bb  = (const float*)d_in[17];
    const float* g2  = (const float*)d_in[18];
    const float* Wp  = (const float*)d_in[19];
    const float* bp  = (const float*)d_in[20];
    float* out = (float*)d_out;

    float* sc = nullptr;
    cudaGetSymbolAddress((void**)&sc, g_scratch);
    float* wt = nullptr;
    cudaGetSymbolAddress((void**)&wt, g_wt);
    float* bc = nullptr;
    cudaGetSymbolAddress((void**)&bc, g_bias);

    const size_t SZ = (size_t)NTOK * DD;
    __nv_bfloat16* hb    = (__nv_bfloat16*)sc;                       // [16384,1024] bf16
    __nv_bfloat16* xb    = (__nv_bfloat16*)(sc + SZ / 2);            // [16384,1024] bf16
    __nv_bfloat16* qkvb  = (__nv_bfloat16*)(sc + 1 * SZ);            // [16384,3072] bf16
    __nv_bfloat16* tanha = (__nv_bfloat16*)(sc + 5 * SZ / 2);        // [16384,1024] bf16
    float* bbuf = sc + 3 * SZ;                                       // [16384,1024] fp32
    float* dn   = sc + 4 * SZ;

    const size_t WSZ = (size_t)DD * DD;
    __nv_bfloat16* Wqkv_t = (__nv_bfloat16*)wt;                      // [3072][1024] bf16
    __nv_bfloat16* Wa_t   = (__nv_bfloat16*)(wt + 3 * WSZ);          // [1024][1024] bf16
    float* Wb_t = wt + 4 * WSZ;                                      // tf32
    float* Wp_t = wt + 5 * WSZ;                                      // tf32

    cudaFuncSetAttribute(gemm_kernel<0>, cudaFuncAttributeMaxDynamicSharedMemorySize, SMEM_GEMM);
    cudaFuncSetAttribute(gemm_kernel<1>, cudaFuncAttributeMaxDynamicSharedMemorySize, SMEM_GEMM);
    cudaFuncSetAttribute(gemm_bf16_kernel<0>, cudaFuncAttributeMaxDynamicSharedMemorySize, SMEM_GEMM);
    cudaFuncSetAttribute(gemm_bf16_kernel<1>, cudaFuncAttributeMaxDynamicSharedMemorySize, SMEM_GEMM);

    // [1] prep
    prep_kernel<<<dim3(32, 32, 7), dim3(32, 8)>>>(Wq, Wk, Wv, Wa, Wb, Wp,
                                                  bq, bk, bv, ba, bb);

    // [2] zc_rms -> hb bf16, xb bf16
    zc_rms_kernel<<<NTOK, 256>>>((const float4*)x, (const float4*)g1,
                                 (uint2*)hb, (uint2*)xb);

    // [3] qkv GEMM (bf16, N = 3072)
    gemm_bf16_kernel<0><<<dim3(24, 128), 128, SMEM_GEMM>>>(hb, Wqkv_t, bc, qkvb, 3072);
    // [4] a GEMM (bf16, N = 1024, tanh epilogue)
    gemm_bf16_kernel<1><<<dim3(8, 128), 128, SMEM_GEMM>>>(xb, Wa_t, bc + 3072, tanha, 1024);
    // [5] b GEMM (tf32, N = 1024, fp32 out)
    gemm_kernel<0><<<dim3(8, 128), 128, SMEM_GEMM>>>(x, Wb_t, bc + 4096, nullptr, bbuf, 1024);

    // [6] fused conv/delta/norm
    conv_delta_kernel<<<NTOK / TCHUNK, 256>>>((const uint2*)qkvb, (const uint2*)tanha,
                                              (const float4*)bbuf,
                                              wqc, bqc, wkc, bkc, wvc, bvc,
                                              (const float4*)g2, (float4*)dn);

    // [7] final GEMM (tf32) + residual epilogue
    gemm_kernel<1><<<dim3(8, 128), 128, SMEM_GEMM>>>(dn, Wp_t, bp, x, out, 1024);
}

// round 17
// speedup vs baseline: 1.4101x; 1.4101x over previous
#include <cuda_runtime.h>
#include <cuda_bf16.h>
#include <cstdint>

#define BB 8
#define TT 2048
#define DD 1024
#define NTOK (BB*TT)       // 16384
#define ROWF4 (DD/4)       // 256

// ---------------- scratch (no allocations allowed) ----------------
// units of SZ=NTOK*DD floats: h bf16 (0..0.5), qkv bf16 (1..2.5), ab fp32 (3..4), dn (5)
__device__ float g_scratch[(size_t)6 * NTOK * DD];
// weights: qkv bf16 transposed [n][k] at 0 (6MB); ab tf32 at +3*WSZ; p tf32 at +5*WSZ
__device__ float g_wt[(size_t)6 * DD * DD];
__device__ float g_bias[5120];                 // bqkv(3072) | bab(2048)

// ---------------- helpers ----------------
__device__ __forceinline__ float sigmoidf_(float x) {
    return 1.0f / (1.0f + __expf(-x));
}
__device__ __forceinline__ float to_tf32(float x) {
    float r;
    asm("cvt.rna.tf32.f32 %0, %1;" : "=f"(r) : "f"(x));
    return r;
}
__device__ __forceinline__ uint32_t s2u(const void* p) {
    return (uint32_t)__cvta_generic_to_shared(p);
}
__device__ __forceinline__ float4 bf4(uint2 u) {
    __nv_bfloat162 lo = *(__nv_bfloat162*)&u.x;
    __nv_bfloat162 hi = *(__nv_bfloat162*)&u.y;
    float2 a = __bfloat1622float2(lo);
    float2 b = __bfloat1622float2(hi);
    return make_float4(a.x, a.y, b.x, b.y);
}

#define MMA_TF32(c, a, b)                                                       \
    asm volatile(                                                               \
        "mma.sync.aligned.m16n8k8.row.col.f32.tf32.tf32.f32 "                   \
        "{%0,%1,%2,%3},{%4,%5,%6,%7},{%8,%9},{%0,%1,%2,%3};\n"                  \
        : "+f"((c)[0]), "+f"((c)[1]), "+f"((c)[2]), "+f"((c)[3])                \
        : "r"((a)[0]), "r"((a)[1]), "r"((a)[2]), "r"((a)[3]),                   \
          "r"((b)[0]), "r"((b)[1]))

#define MMA_BF16(c, a, b)                                                       \
    asm volatile(                                                               \
        "mma.sync.aligned.m16n8k16.row.col.f32.bf16.bf16.f32 "                  \
        "{%0,%1,%2,%3},{%4,%5,%6,%7},{%8,%9},{%0,%1,%2,%3};\n"                  \
        : "+f"((c)[0]), "+f"((c)[1]), "+f"((c)[2]), "+f"((c)[3])                \
        : "r"((a)[0]), "r"((a)[1]), "r"((a)[2]), "r"((a)[3]),                   \
          "r"((b)[0]), "r"((b)[1]))

#define LDSM4(r0, r1, r2, r3, addr)                                             \
    asm volatile("ldmatrix.sync.aligned.m8n8.x4.shared.b16 {%0,%1,%2,%3}, [%4];"\
        : "=r"(r0), "=r"(r1), "=r"(r2), "=r"(r3) : "r"(addr))

#define CP16(smem_addr, gptr)                                                   \
    asm volatile("cp.async.cg.shared.global [%0], [%1], 16;"                    \
                 :: "r"(smem_addr), "l"(gptr) : "memory")
#define CP_COMMIT() asm volatile("cp.async.commit_group;" ::: "memory")

// ---------------- prep: transpose weights (qkv->bf16, ab/p->tf32); bias concat ----------------
__global__ void prep_kernel(const float* __restrict__ Wq, const float* __restrict__ Wk,
                            const float* __restrict__ Wv, const float* __restrict__ Wa,
                            const float* __restrict__ Wb, const float* __restrict__ Wp,
                            const float* __restrict__ bq, const float* __restrict__ bk,
                            const float* __restrict__ bv, const float* __restrict__ ba,
                            const float* __restrict__ bb) {
    const int s = blockIdx.z;
    if (s == 6) {
        if (blockIdx.x != 0 || blockIdx.y != 0) return;
        const int tid = threadIdx.y * 32 + threadIdx.x;
        for (int i = tid; i < 1024; i += 256) {
            g_bias[i]        = bq[i];
            g_bias[1024 + i] = bk[i];
            g_bias[2048 + i] = bv[i];
            g_bias[3072 + i] = ba[i];
            g_bias[4096 + i] = bb[i];
        }
        return;
    }
    const float* srcs[6] = {Wq, Wk, Wv, Wa, Wb, Wp};
    const float* S = srcs[s];
    __shared__ float t[32][33];
    const int bx = blockIdx.x * 32, by = blockIdx.y * 32;
    const int tx = threadIdx.x, ty = threadIdx.y;
#pragma unroll
    for (int i = 0; i < 4; i++)
        t[ty + 8 * i][tx] = S[(size_t)(by + ty + 8 * i) * DD + bx + tx];
    __syncthreads();
    if (s < 3) {
        // bf16 transposed: rows n (s*1024 + bx + r), k contiguous
        __nv_bfloat16* D16 = (__nv_bfloat16*)g_wt + (size_t)s * DD * DD;
#pragma unroll
        for (int i = 0; i < 4; i++)
            D16[(size_t)(bx + ty + 8 * i) * DD + by + tx] =
                __float2bfloat16(t[tx][ty + 8 * i]);
    } else {
        float* D = g_wt + (size_t)s * DD * DD;
#pragma unroll
        for (int i = 0; i < 4; i++)
            D[(size_t)(bx + ty + 8 * i) * DD + by + tx] = to_tf32(t[tx][ty + 8 * i]);
    }
}

// ---------------- zc_rms: h = bf16(zc_rms(x)) ----------------
__global__ void zc_rms_kernel(const float4* __restrict__ x,
                              const float4* __restrict__ g,
                              uint2* __restrict__ out) {
    __shared__ float red[16];
    const int row = blockIdx.x;
    const int tid = threadIdx.x;
    const size_t base = (size_t)row * ROWF4 + tid;

    float4 v = x[base];
    float s  = v.x + v.y + v.z + v.w;
    float s2 = v.x*v.x + v.y*v.y + v.z*v.z + v.w*v.w;
#pragma unroll
    for (int o = 16; o; o >>= 1) {
        s  += __shfl_xor_sync(0xffffffffu, s,  o);
        s2 += __shfl_xor_sync(0xffffffffu, s2, o);
    }
    const int w = tid >> 5, l = tid & 31;
    if (l == 0) { red[w] = s; red[8 + w] = s2; }
    __syncthreads();
    s = 0.f; s2 = 0.f;
#pragma unroll
    for (int i = 0; i < 8; i++) { s += red[i]; s2 += red[8 + i]; }

    const float mean = s * (1.0f / DD);
    const float var  = s2 * (1.0f / DD) - mean * mean;
    const float r    = rsqrtf(var + 1e-8f);

    float4 gv = g[tid];
    __nv_bfloat162 lo = __floats2bfloat162_rn((v.x - mean) * r * gv.x,
                                              (v.y - mean) * r * gv.y);
    __nv_bfloat162 hi = __floats2bfloat162_rn((v.z - mean) * r * gv.z,
                                              (v.w - mean) * r * gv.w);
    uint2 o;
    o.x = *(uint32_t*)&lo;
    o.y = *(uint32_t*)&hi;
    out[base] = o;
}

// ---------------- fused conv3+sigmoid (q,k,v bf16) + l2norm + delta + zc_rms ----------------
#define TCHUNK 8
__global__ void conv_delta_kernel(const uint2* __restrict__ qkv,
                                  const float4* __restrict__ ab,
                                  const float* __restrict__ wq, const float* __restrict__ cbq,
                                  const float* __restrict__ wk, const float* __restrict__ cbk,
                                  const float* __restrict__ wv, const float* __restrict__ cbv,
                                  const float4* __restrict__ g2,
                                  float4* __restrict__ out) {
    __shared__ float redA[2][16];
    __shared__ float redB[2][16];
    const int row0 = blockIdx.x * TCHUNK;
    const int tid = threadIdx.x;
    const int t0 = row0 & (TT - 1);
    const int d0 = tid * 4;
    const int w = tid >> 5, l = tid & 31;

    float cw[3][12], cbr[3][4];
#pragma unroll
    for (int j = 0; j < 4; j++) {
#pragma unroll
        for (int c = 0; c < 3; c++) {
            cw[0][j * 3 + c] = wq[(d0 + j) * 3 + c];
            cw[1][j * 3 + c] = wk[(d0 + j) * 3 + c];
            cw[2][j * 3 + c] = wv[(d0 + j) * 3 + c];
        }
        cbr[0][j] = cbq[d0 + j];
        cbr[1][j] = cbk[d0 + j];
        cbr[2][j] = cbv[d0 + j];
    }
    const float4 g2v = g2[tid];

    const size_t qbase = (size_t)row0 * 768 + tid;
    const float4 Z = make_float4(0.f, 0.f, 0.f, 0.f);

    float4 qm, qc, km, kc, vm, vc;
    qc = bf4(qkv[qbase]);
    kc = bf4(qkv[qbase + 256]);
    vc = bf4(qkv[qbase + 512]);
    if (t0 > 0) {
        qm = bf4(qkv[qbase - 768]);
        km = bf4(qkv[qbase - 768 + 256]);
        vm = bf4(qkv[qbase - 768 + 512]);
    } else { qm = Z; km = Z; vm = Z; }

    for (int i = 0; i < TCHUNK; i++) {
        const int row = row0 + i;
        const int t = t0 + i;
        const size_t qb = qbase + (size_t)i * 768;
        float4 qp, kp, vp;
        if (t < TT - 1) {
            qp = bf4(qkv[qb + 768]);
            kp = bf4(qkv[qb + 768 + 256]);
            vp = bf4(qkv[qb + 768 + 512]);
        } else { qp = Z; kp = Z; vp = Z; }

        const size_t abb = (size_t)row * 512 + tid;
        float4 av = ab[abb], bv = ab[abb + 256];

        float4 qv, kv, vv;
#define C1(st, j, m, c, p) sigmoidf_(fmaf(cw[st][j*3+0], (m), fmaf(cw[st][j*3+1], (c), fmaf(cw[st][j*3+2], (p), cbr[st][j]))))
        qv.x = C1(0, 0, qm.x, qc.x, qp.x); qv.y = C1(0, 1, qm.y, qc.y, qp.y);
        qv.z = C1(0, 2, qm.z, qc.z, qp.z); qv.w = C1(0, 3, qm.w, qc.w, qp.w);
        kv.x = C1(1, 0, km.x, kc.x, kp.x); kv.y = C1(1, 1, km.y, kc.y, kp.y);
        kv.z = C1(1, 2, km.z, kc.z, kp.z); kv.w = C1(1, 3, km.w, kc.w, kp.w);
        vv.x = C1(2, 0, vm.x, vc.x, vp.x); vv.y = C1(2, 1, vm.y, vc.y, vp.y);
        vv.z = C1(2, 2, vm.z, vc.z, vp.z); vv.w = C1(2, 3, vm.w, vc.w, vp.w);
#undef C1
        qm = qc; qc = qp; km = kc; kc = kp; vm = vc; vc = vp;

        const int par = i & 1;
        float sq = qv.x*qv.x + qv.y*qv.y + qv.z*qv.z + qv.w*qv.w;
        float sk = kv.x*kv.x + kv.y*kv.y + kv.z*kv.z + kv.w*kv.w;
#pragma unroll
        for (int o = 16; o; o >>= 1) {
            sq += __shfl_xor_sync(0xffffffffu, sq, o);
            sk += __shfl_xor_sync(0xffffffffu, sk, o);
        }
        if (l == 0) { redA[par][w] = sq; redA[par][8 + w] = sk; }
        __syncthreads();
        sq = 0.f; sk = 0.f;
#pragma unroll
        for (int j = 0; j < 8; j++) { sq += redA[par][j]; sk += redA[par][8 + j]; }

        const float rq = rsqrtf(sq + 1e-8f);
        const float rk = rsqrtf(sk + 1e-8f);

        float dd0 = fmaf(tanhf(av.x), (qv.x*rq)*(kv.x*rk)*vv.x, bv.x);
        float dd1 = fmaf(tanhf(av.y), (qv.y*rq)*(kv.y*rk)*vv.y, bv.y);
        float dd2 = fmaf(tanhf(av.z), (qv.z*rq)*(kv.z*rk)*vv.z, bv.z);
        float dd3 = fmaf(tanhf(av.w), (qv.w*rq)*(kv.w*rk)*vv.w, bv.w);

        float s  = dd0 + dd1 + dd2 + dd3;
        float s2 = dd0*dd0 + dd1*dd1 + dd2*dd2 + dd3*dd3;
#pragma unroll
        for (int o = 16; o; o >>= 1) {
            s  += __shfl_xor_sync(0xffffffffu, s,  o);
            s2 += __shfl_xor_sync(0xffffffffu, s2, o);
        }
        if (l == 0) { redB[par][w] = s; redB[par][8 + w] = s2; }
        __syncthreads();
        s = 0.f; s2 = 0.f;
#pragma unroll
        for (int j = 0; j < 8; j++) { s += redB[par][j]; s2 += redB[par][8 + j]; }

        const float mean = s * (1.0f / DD);
        const float var  = s2 * (1.0f / DD) - mean * mean;
        const float r    = rsqrtf(var + 1e-8f);

        float4 o;
        o.x = to_tf32((dd0 - mean) * r * g2v.x);
        o.y = to_tf32((dd1 - mean) * r * g2v.y);
        o.z = to_tf32((dd2 - mean) * r * g2v.z);
        o.w = to_tf32((dd3 - mean) * r * g2v.w);
        out[(size_t)row * ROWF4 + tid] = o;
    }
}

// ======================= tf32 GEMM (R10 winner) =======================
#define TPITCH   144
#define AS_BYTES (128 * TPITCH)
#define BS_BYTES (128 * TPITCH)
#define STAGE_BYTES (AS_BYTES + BS_BYTES)        // 36864
#define NUM_STAGES 3
#define SMEM_GEMM (NUM_STAGES * STAGE_BYTES)     // 110592 (2 CTA/SM)

template <int EPI>   // 0: fp32 out; 1: residual epilogue
__global__ __launch_bounds__(128, 2)
void gemm_kernel(const float* __restrict__ A,
                 const float* __restrict__ Wt,
                 const float* __restrict__ bias,
                 const float* __restrict__ X,
                 float* __restrict__ C, const int ldc) {
    extern __shared__ __align__(16) char smem[];
    const int tid = threadIdx.x;
    const int m0 = blockIdx.y * 128;
    const int n0 = blockIdx.x * 128;
    const int warp = tid >> 5, lane = tid & 31;
    const int g = lane >> 2, tg = lane & 3;
    const int mBase = (warp >> 1) * 64;
    const int nBase = (warp & 1) * 64;

    const uint32_t smem_u = s2u(smem);

    const int rowL = tid >> 3, k4L = tid & 7;
    const float* gA = A  + (size_t)(m0 + rowL) * DD + k4L * 4;
    const float* gB = Wt + (size_t)(n0 + rowL) * DD + k4L * 4;

    const int q = lane >> 3, e = lane & 7;
    uint32_t aoff[4], boff[4];
#pragma unroll
    for (int mi = 0; mi < 4; mi++)
        aoff[mi] = (uint32_t)((mBase + mi * 16 + e + ((q & 1) << 3)) * TPITCH + ((q >> 1) << 4));
#pragma unroll
    for (int p = 0; p < 4; p++)
        boff[p] = (uint32_t)((nBase + p * 16 + ((q >> 1) << 3) + e) * TPITCH + ((q & 1) << 4));

    float acc[4][8][4];
#pragma unroll
    for (int mi = 0; mi < 4; mi++)
#pragma unroll
        for (int ni = 0; ni < 8; ni++)
#pragma unroll
            for (int i = 0; i < 4; i++) acc[mi][ni][i] = 0.f;

#define LOAD_CHUNK(k0, stage)                                                   \
    {                                                                           \
        const uint32_t sA0 = smem_u + (stage) * STAGE_BYTES;                    \
        const uint32_t sB0 = sA0 + AS_BYTES;                                    \
        _Pragma("unroll")                                                       \
        for (int i = 0; i < 8; i++)                                             \
            CP16(sA0 + (rowL + i * 16) * TPITCH + k4L * 16,                     \
                 gA + (size_t)(i * 16) * DD + (k0));                            \
        _Pragma("unroll")                                                       \
        for (int i = 0; i < 8; i++)                                             \
            CP16(sB0 + (rowL + i * 16) * TPITCH + k4L * 16,                     \
                 gB + (size_t)(i * 16) * DD + (k0));                            \
    }

#define FRAG_LOAD(b, kb)                                                        \
    {                                                                           \
        _Pragma("unroll")                                                       \
        for (int mi = 0; mi < 4; mi++)                                          \
            LDSM4(af[b][mi][0], af[b][mi][1], af[b][mi][2], af[b][mi][3],       \
                  sA + aoff[mi] + (kb));                                        \
        _Pragma("unroll")                                                       \
        for (int p = 0; p < 4; p++)                                             \
            LDSM4(bf[b][2 * p][0], bf[b][2 * p][1],                             \
                  bf[b][2 * p + 1][0], bf[b][2 * p + 1][1],                     \
                  sB + boff[p] + (kb));                                         \
    }

    LOAD_CHUNK(0, 0);  CP_COMMIT();
    LOAD_CHUNK(32, 1); CP_COMMIT();

    uint32_t af[2][4][4], bf[2][8][2];

    for (int kt = 0; kt < 32; ++kt) {
        if (kt < 31) asm volatile("cp.async.wait_group 1;" ::: "memory");
        else         asm volatile("cp.async.wait_group 0;" ::: "memory");
        __syncthreads();

        const int s = kt % 3;
        const uint32_t sA = smem_u + s * STAGE_BYTES;
        const uint32_t sB = sA + AS_BYTES;

        const bool doPf = (kt + 2 < 32);
        const int pfk0 = (kt + 2) * 32;
        const int pfs = (kt + 2) % 3;
        const uint32_t pA = smem_u + pfs * STAGE_BYTES;
        const uint32_t pB = pA + AS_BYTES;

        FRAG_LOAD(0, 0);

#pragma unroll
        for (int kk8 = 0; kk8 < 4; kk8++) {
            const int cur = kk8 & 1;
            if (doPf) {
#pragma unroll
                for (int j = 0; j < 2; j++) {
                    const int i = kk8 * 2 + j;
                    CP16(pA + (rowL + i * 16) * TPITCH + k4L * 16,
                         gA + (size_t)(i * 16) * DD + pfk0);
                    CP16(pB + (rowL + i * 16) * TPITCH + k4L * 16,
                         gB + (size_t)(i * 16) * DD + pfk0);
                }
            }
            if (kk8 < 3) {
                const int nxt = cur ^ 1;
                const uint32_t kbn = (kk8 + 1) * 32;
                FRAG_LOAD(nxt, kbn);
            }
#pragma unroll
            for (int mi = 0; mi < 4; mi++)
#pragma unroll
                for (int ni = 0; ni < 8; ni++)
                    MMA_TF32(acc[mi][ni], af[cur][mi], bf[cur][ni]);
        }
        if (doPf) CP_COMMIT();
    }
#undef LOAD_CHUNK
#undef FRAG_LOAD

#pragma unroll
    for (int mi = 0; mi < 4; mi++) {
#pragma unroll
        for (int ni = 0; ni < 8; ni++) {
            const int r = m0 + mBase + mi * 16 + g;
            const int c = n0 + nBase + ni * 8 + 2 * tg;
            const float b0 = __ldg(bias + c);
            const float b1 = __ldg(bias + c + 1);
#pragma unroll
            for (int half = 0; half < 2; half++) {
                const int rr = r + half * 8;
                float da = acc[mi][ni][half * 2 + 0] + b0;
                float db = acc[mi][ni][half * 2 + 1] + b1;
                if (EPI == 1) {
                    const float sa = da * sigmoidf_(da);   // silu
                    const float sb = db * sigmoidf_(db);
                    const float2 xv = *(const float2*)(X + (size_t)rr * DD + c);
                    *(float2*)(C + (size_t)rr * ldc + c) =
                        make_float2(xv.x + sigmoidf_(sa) * da,
                                    xv.y + sigmoidf_(sb) * db);
                } else {
                    *(float2*)(C + (size_t)rr * ldc + c) = make_float2(da, db);
                }
            }
        }
    }
}

// ======================= bf16 GEMM (qkv), m16n8k16 =======================
__global__ __launch_bounds__(128, 2)
void gemm_bf16_kernel(const __nv_bfloat16* __restrict__ A,
                      const __nv_bfloat16* __restrict__ Wt,  // [n][k], pitch 1024
                      const float* __restrict__ bias,
                      __nv_bfloat16* __restrict__ C, const int ldc) {
    extern __shared__ __align__(16) char smem[];
    const int tid = threadIdx.x;
    const int m0 = blockIdx.y * 128;
    const int n0 = blockIdx.x * 128;
    const int warp = tid >> 5, lane = tid & 31;
    const int g = lane >> 2, tg = lane & 3;
    const int mBase = (warp >> 1) * 64;
    const int nBase = (warp & 1) * 64;

    const uint32_t smem_u = s2u(smem);

    const int rowL = tid >> 3, k4L = tid & 7;
    const __nv_bfloat16* gA = A  + (size_t)(m0 + rowL) * DD + k4L * 8;
    const __nv_bfloat16* gB = Wt + (size_t)(n0 + rowL) * DD + k4L * 8;

    const int q = lane >> 3, e = lane & 7;
    uint32_t aoff[4], boff[4];
#pragma unroll
    for (int mi = 0; mi < 4; mi++)
        aoff[mi] = (uint32_t)((mBase + mi * 16 + e + ((q & 1) << 3)) * TPITCH + ((q >> 1) << 4));
#pragma unroll
    for (int p = 0; p < 4; p++)
        boff[p] = (uint32_t)((nBase + p * 16 + ((q >> 1) << 3) + e) * TPITCH + ((q & 1) << 4));

    float acc[4][8][4];
#pragma unroll
    for (int mi = 0; mi < 4; mi++)
#pragma unroll
        for (int ni = 0; ni < 8; ni++)
#pragma unroll
            for (int i = 0; i < 4; i++) acc[mi][ni][i] = 0.f;

#define LOAD_CHUNK_B(k0, stage)                                                 \
    {                                                                           \
        const uint32_t sA0 = smem_u + (stage) * STAGE_BYTES;                    \
        const uint32_t sB0 = sA0 + AS_BYTES;                                    \
        _Pragma("unroll")                                                       \
        for (int i = 0; i < 8; i++)                                             \
            CP16(sA0 + (rowL + i * 16) * TPITCH + k4L * 16,                     \
                 gA + (size_t)(i * 16) * DD + (k0));                            \
        _Pragma("unroll")                                                       \
        for (int i = 0; i < 8; i++)                                             \
            CP16(sB0 + (rowL + i * 16) * TPITCH + k4L * 16,                     \
                 gB + (size_t)(i * 16) * DD + (k0));                            \
    }

#define FRAG_LOAD_B(b, kb)                                                      \
    {                                                                           \
        _Pragma("unroll")                                                       \
        for (int mi = 0; mi < 4; mi++)                                          \
            LDSM4(af[b][mi][0], af[b][mi][1], af[b][mi][2], af[b][mi][3],       \
                  sA + aoff[mi] + (kb));                                        \
        _Pragma("unroll")                                                       \
        for (int p = 0; p < 4; p++)                                             \
            LDSM4(bf[b][2 * p][0], bf[b][2 * p][1],                             \
                  bf[b][2 * p + 1][0], bf[b][2 * p + 1][1],                     \
                  sB + boff[p] + (kb));                                         \
    }

    LOAD_CHUNK_B(0, 0);  CP_COMMIT();
    LOAD_CHUNK_B(64, 1); CP_COMMIT();

    uint32_t af[2][4][4], bf[2][8][2];

    for (int kt = 0; kt < 16; ++kt) {
        if (kt < 15) asm volatile("cp.async.wait_group 1;" ::: "memory");
        else         asm volatile("cp.async.wait_group 0;" ::: "memory");
        __syncthreads();

        const int s = kt % 3;
        const uint32_t sA = smem_u + s * STAGE_BYTES;
        const uint32_t sB = sA + AS_BYTES;

        const bool doPf = (kt + 2 < 16);
        const int pfk0 = (kt + 2) * 64;
        const int pfs = (kt + 2) % 3;
        const uint32_t pA = smem_u + pfs * STAGE_BYTES;
        const uint32_t pB = pA + AS_BYTES;

        FRAG_LOAD_B(0, 0);

#pragma unroll
        for (int kk8 = 0; kk8 < 4; kk8++) {   // each step covers k=16
            const int cur = kk8 & 1;
            if (doPf) {
#pragma unroll
                for (int j = 0; j < 2; j++) {
                    const int i = kk8 * 2 + j;
                    CP16(pA + (rowL + i * 16) * TPITCH + k4L * 16,
                         gA + (size_t)(i * 16) * DD + pfk0);
                    CP16(pB + (rowL + i * 16) * TPITCH + k4L * 16,
                         gB + (size_t)(i * 16) * DD + pfk0);
                }
            }
            if (kk8 < 3) {
                const int nxt = cur ^ 1;
                const uint32_t kbn = (kk8 + 1) * 32;   // 16 bf16 = 32 bytes
                FRAG_LOAD_B(nxt, kbn);
            }
#pragma unroll
            for (int mi = 0; mi < 4; mi++)
#pragma unroll
                for (int ni = 0; ni < 8; ni++)
                    MMA_BF16(acc[mi][ni], af[cur][mi], bf[cur][ni]);
        }
        if (doPf) CP_COMMIT();
    }
#undef LOAD_CHUNK_B
#undef FRAG_LOAD_B

    // epilogue: bias + bf16 pack
#pragma unroll
    for (int mi = 0; mi < 4; mi++) {
#pragma unroll
        for (int ni = 0; ni < 8; ni++) {
            const int r = m0 + mBase + mi * 16 + g;
            const int c = n0 + nBase + ni * 8 + 2 * tg;
            const float b0 = __ldg(bias + c);
            const float b1 = __ldg(bias + c + 1);
#pragma unroll
            for (int half = 0; half < 2; half++) {
                const int rr = r + half * 8;
                __nv_bfloat162 pk = __floats2bfloat162_rn(
                    acc[mi][ni][half * 2 + 0] + b0,
                    acc[mi][ni][half * 2 + 1] + b1);
                *(__nv_bfloat162*)(C + (size_t)rr * ldc + c) = pk;
            }
        }
    }
}

// ---------------- launch ----------------
extern "C" void kernel_launch(void* const* d_in, const int* in_sizes, int n_in,
                              void* d_out, int out_size) {
    const float* x   = (const float*)d_in[0];
    const float* g1  = (const float*)d_in[1];
    const float* Wq  = (const float*)d_in[2];
    const float* bq  = (const float*)d_in[3];
    const float* Wk  = (const float*)d_in[4];
    const float* bk  = (const float*)d_in[5];
    const float* Wv  = (const float*)d_in[6];
    const float* bv  = (const float*)d_in[7];
    const float* wqc = (const float*)d_in[8];
    const float* bqc = (const float*)d_in[9];
    const float* wkc = (const float*)d_in[10];
    const float* bkc = (const float*)d_in[11];
    const float* wvc = (const float*)d_in[12];
    const float* bvc = (const float*)d_in[13];
    const float* Wa  = (const float*)d_in[14];
    const float* ba  = (const float*)d_in[15];
    const float* Wb  = (const float*)d_in[16];
    const float* bb  = (const float*)d_in[17];
    const float* g2  = (const float*)d_in[18];
    const float* Wp  = (const float*)d_in[19];
    const float* bp  = (const float*)d_in[20];
    float* out = (float*)d_out;

    float* sc = nullptr;
    cudaGetSymbolAddress((void**)&sc, g_scratch);
    float* wt = nullptr;
    cudaGetSymbolAddress((void**)&wt, g_wt);
    float* bc = nullptr;
    cudaGetSymbolAddress((void**)&bc, g_bias);

    const size_t SZ = (size_t)NTOK * DD;
    __nv_bfloat16* hb = (__nv_bfloat16*)(sc + 0 * SZ);   // [16384,1024] bf16
    __nv_bfloat16* qkvb = (__nv_bfloat16*)(sc + 1 * SZ); // [16384,3072] bf16
    float* abp  = sc + 3 * SZ;                           // [16384,2048] fp32
    float* dn   = sc + 5 * SZ;

    const size_t WSZ = (size_t)DD * DD;
    __nv_bfloat16* Wqkv_t = (__nv_bfloat16*)wt;          // [3072][1024] bf16
    float* Wab_t  = wt + 3 * WSZ;
    float* Wp_t   = wt + 5 * WSZ;

    cudaFuncSetAttribute(gemm_kernel<0>, cudaFuncAttributeMaxDynamicSharedMemorySize, SMEM_GEMM);
    cudaFuncSetAttribute(gemm_kernel<1>, cudaFuncAttributeMaxDynamicSharedMemorySize, SMEM_GEMM);
    cudaFuncSetAttribute(gemm_bf16_kernel, cudaFuncAttributeMaxDynamicSharedMemorySize, SMEM_GEMM);

    // [1] prep (weight transpose: qkv->bf16, ab/p->tf32; bias concat)
    prep_kernel<<<dim3(32, 32, 7), dim3(32, 8)>>>(Wq, Wk, Wv, Wa, Wb, Wp,
                                                  bq, bk, bv, ba, bb);

    // [2] zc_rms -> h bf16
    zc_rms_kernel<<<NTOK, 256>>>((const float4*)x, (const float4*)g1, (uint2*)hb);

    // [3] qkv GEMM (bf16 m16n8k16, N = 3072, bf16 out)
    gemm_bf16_kernel<<<dim3(24, 128), 128, SMEM_GEMM>>>(hb, Wqkv_t, bc, qkvb, 3072);
    // [4] ab GEMM (tf32, N = 2048, fp32 out)
    gemm_kernel<0><<<dim3(16, 128), 128, SMEM_GEMM>>>(x, Wab_t, bc + 3072, nullptr, abp, 2048);

    // [5] fused conv/delta/norm (bf16 qkv)
    conv_delta_kernel<<<NTOK / TCHUNK, 256>>>((const uint2*)qkvb, (const float4*)abp,
                                              wqc, bqc, wkc, bkc, wvc, bvc,
                                              (const float4*)g2, (float4*)dn);

    // [6] final GEMM (tf32) + residual epilogue
    gemm_kernel<1><<<dim3(8, 128), 128, SMEM_GEMM>>>(dn, Wp_t, bp, x, out, 1024);
}